// round 10
// baseline (speedup 1.0000x reference)
#include <cuda_runtime.h>
#include <stdint.h>

// ---------------- static device scratch (no allocations allowed) ----------------
#define SBINS 65536
#define LBINS 4096
#define BUFCAP (4u<<20)

__device__ unsigned g_shist[SBINS];
__device__ unsigned g_lvlhist[2][LBINS];
__device__ unsigned g_bufCount[2];
__device__ unsigned g_cntBelow[2];
__device__ unsigned g_bkA[2];
__device__ unsigned g_bkB[2];
__device__ unsigned g_stS[2], g_stPM[2], g_stPV[2], g_stR[2];
__device__ float    g_thresh[2];
__device__ unsigned g_buf[2][BUFCAP];

// monotonic uint32 key: preserves float total order
__device__ __forceinline__ unsigned fkey(float f){
    unsigned b = __float_as_uint(f);
    return b ^ ((unsigned)(((int)b) >> 31) | 0x80000000u);
}
__device__ __forceinline__ float keyToFloat(unsigned k){
    unsigned b = (k & 0x80000000u) ? (k ^ 0x80000000u) : ~k;
    return __uint_as_float(b);
}

// ---------------- K0: zero scratch ----------------
__global__ void __launch_bounds__(256) k_zero(){
    int i  = blockIdx.x*blockDim.x + threadIdx.x;
    int st = gridDim.x*blockDim.x;
    for (int j=i; j<SBINS; j+=st) g_shist[j]=0;
    for (int j=i; j<2*LBINS; j+=st) (&g_lvlhist[0][0])[j]=0;
    if (i<2){ g_bufCount[i]=0; g_cntBelow[i]=0; }
}

// ---------------- K1: strided sample -> 16-bit-key histogram ----------------
__global__ void __launch_bounds__(256) k_sample(const float* __restrict__ x, long long n, int stride){
    long long s = (long long)(blockIdx.x*blockDim.x + threadIdx.x);
    long long i = s * (long long)stride;
    if (i < n){
        unsigned k = fkey(x[i]);
        atomicAdd(&g_shist[k>>16], 1u);
    }
}

// ---------------- K2: bracket both target ranks from sample CDF ----------------
__global__ void __launch_bounds__(1024,1) k_bracket(unsigned tsLo, unsigned tsHi, unsigned M){
    __shared__ unsigned ps[1024];
    __shared__ int aBin[2]; __shared__ int bBin[2];
    int tid  = threadIdx.x;
    int base = tid*64;
    unsigned s = 0;
    for (int j=0;j<64;j++) s += g_shist[base+j];
    ps[tid]=s;
    if (tid<2){ aBin[tid]=0; bBin[tid]=SBINS; }
    __syncthreads();
    for (int off=1; off<1024; off<<=1){
        unsigned v = (tid>=off)? ps[tid-off] : 0u;
        __syncthreads();
        ps[tid] += v;
        __syncthreads();
    }
    unsigned segExcl = ps[tid]-s;
    unsigned TA[2]; TA[0] = (tsLo>M)? tsLo-M:0u; TA[1] = (tsHi>M)? tsHi-M:0u;
    unsigned TB[2]; TB[0] = tsLo+M; TB[1] = tsHi+M;
    for (int t=0;t<2;t++){
        // largest boundary i with cum(i) <= TA  ->  a = i<<16  (cum monotone -> prefix set)
        unsigned run = segExcl; int best = -1;
        for (int j=0;j<64;j++){
            if (run <= TA[t]) best = base+j;
            run += g_shist[base+j];
        }
        if (best>=0) atomicMax(&aBin[t], best);
        // smallest boundary i with cum(i) >= TB -> b = i<<16
        run = segExcl;
        for (int j=0;j<64;j++){
            if (run >= TB[t]) { atomicMin(&bBin[t], base+j); break; }
            run += g_shist[base+j];
        }
    }
    __syncthreads();
    if (tid<2){
        int t = tid;
        unsigned a  = ((unsigned)aBin[t]) << 16;
        unsigned bb = (bBin[t] >= SBINS) ? 0xFFFFFFFFu : (((unsigned)bBin[t]) << 16);
        if (bb <= a) bb = a + 0x10000u;
        g_bkA[t]=a; g_bkB[t]=bb;
        unsigned W  = bb - a;                     // >= 0x10000
        unsigned L  = 32u - __clz(W - 1u);        // bits needed for window offsets
        unsigned s1 = (L>12u)? L-12u : 0u;
        g_stS[t]=s1; g_stPM[t]=0u; g_stPV[t]=0u; g_stR[t]=0u;
    }
}

// ---------------- K3: full scan — exact counts below a, ballot-aggregated collect ----------------
__global__ void __launch_bounds__(256) k_collect(const float4* __restrict__ x4, int n4){
    unsigned a0=g_bkA[0], b0=g_bkB[0], a1=g_bkA[1], b1=g_bkB[1];
    unsigned c0=0, c1=0;
    int tid = threadIdx.x;
    int lane = tid & 31;
    int idx = blockIdx.x*blockDim.x + tid;
    int st  = gridDim.x*blockDim.x;
    int iters = (n4 + st - 1) / st;          // uniform trip count: ballots always full-warp
    for (int it=0; it<iters; it++){
        int i = idx + it*st;
        bool inb = (i < n4);
        float4 v = make_float4(0.f,0.f,0.f,0.f);
        if (inb) v = x4[i];
        float vv[4] = {v.x, v.y, v.z, v.w};
        #pragma unroll
        for (int e=0;e<4;e++){
            unsigned k = fkey(vv[e]);
            c0 += (unsigned)(inb & (k < a0));
            c1 += (unsigned)(inb & (k < a1));
            bool w0 = inb && (k >= a0) && (k < b0);
            bool w1 = inb && (k >= a1) && (k < b1);
            unsigned m0 = __ballot_sync(0xFFFFFFFFu, w0);
            if (m0){
                int leader = __ffs(m0)-1;
                unsigned base = 0;
                if (lane == leader) base = atomicAdd(&g_bufCount[0], (unsigned)__popc(m0));
                base = __shfl_sync(0xFFFFFFFFu, base, leader);
                if (w0){
                    unsigned g = base + (unsigned)__popc(m0 & ((1u<<lane)-1u));
                    if (g < BUFCAP) g_buf[0][g] = k;
                }
            }
            unsigned m1 = __ballot_sync(0xFFFFFFFFu, w1);
            if (m1){
                int leader = __ffs(m1)-1;
                unsigned base = 0;
                if (lane == leader) base = atomicAdd(&g_bufCount[1], (unsigned)__popc(m1));
                base = __shfl_sync(0xFFFFFFFFu, base, leader);
                if (w1){
                    unsigned g = base + (unsigned)__popc(m1 & ((1u<<lane)-1u));
                    if (g < BUFCAP) g_buf[1][g] = k;
                }
            }
        }
    }
    // warp-reduce exact below-window counts, 2 global atomics per warp
    #pragma unroll
    for (int o=16;o>0;o>>=1){
        c0 += __shfl_down_sync(0xFFFFFFFFu, c0, o);
        c1 += __shfl_down_sync(0xFFFFFFFFu, c1, o);
    }
    if (lane == 0){
        atomicAdd(&g_cntBelow[0], c0);
        atomicAdd(&g_cntBelow[1], c1);
    }
}

// ---------------- K4: one radix level over the window buffer (both thresholds) ----------------
__global__ void __launch_bounds__(256) k_lvl(){
    __shared__ unsigned h[LBINS];
    int t   = blockIdx.y;
    int tid = threadIdx.x;
    for (int j=tid; j<LBINS; j+=blockDim.x) h[j]=0;
    __syncthreads();
    unsigned nb = min(g_bufCount[t], (unsigned)BUFCAP);
    unsigned s  = g_stS[t], pm = g_stPM[t], pv = g_stPV[t], a = g_bkA[t];
    unsigned idx = blockIdx.x*blockDim.x + tid;
    unsigned st  = gridDim.x*blockDim.x;
    for (unsigned i=idx; i<nb; i+=st){
        unsigned v = g_buf[t][i] - a;
        if ((v & pm) == pv) atomicAdd(&h[(v>>s) & (LBINS-1)], 1u);
    }
    __syncthreads();
    for (int j=tid; j<LBINS; j+=blockDim.x)
        if (h[j]) atomicAdd(&g_lvlhist[t][j], h[j]);
}

// ---------------- K5: scan level histogram, narrow selection; level 3 emits threshold ----------------
__global__ void __launch_bounds__(1024,1) k_scan(int level, unsigned pLo, unsigned pHi){
    __shared__ unsigned ps[1024];
    __shared__ unsigned sd, snr;
    int t   = blockIdx.x;
    int tid = threadIdx.x;
    if (tid == 0){ sd = LBINS-1; snr = 0; }   // defensive init (covered by scan-loop syncs)
    unsigned c[4];
    int base = tid*4;
    unsigned s4=0;
    #pragma unroll
    for (int j=0;j<4;j++){ c[j]=g_lvlhist[t][base+j]; s4+=c[j]; }
    ps[tid]=s4; __syncthreads();
    for (int off=1; off<1024; off<<=1){
        unsigned v = (tid>=off)? ps[tid-off] : 0u;
        __syncthreads();
        ps[tid] += v;
        __syncthreads();
    }
    unsigned total = ps[1023];
    unsigned r;
    if (level==1){
        unsigned p = (t==0)? pLo : pHi;
        unsigned below = g_cntBelow[t];
        r = (p >= below) ? (p - below) : 0u;  // rank inside the window buffer, clamped
    } else r = g_stR[t];
    if (total > 0 && r >= total) r = total - 1u;   // never let r escape the histogram
    unsigned segExcl = ps[tid]-s4;
    if (segExcl <= r && r < ps[tid]){   // exactly one thread matches
        unsigned run = segExcl;
        #pragma unroll
        for (int j=0;j<4;j++){
            if (r < run + c[j]){ sd = (unsigned)(base+j); snr = r - run; break; }
            run += c[j];
        }
    }
    __syncthreads();
    if (tid==0){
        unsigned s  = g_stS[t];
        unsigned pv = g_stPV[t] | (sd << s);
        g_stPV[t] = pv;
        g_stPM[t] = g_stPM[t] | (0xFFFu << s);
        g_stS[t]  = (s>=12u)? s-12u : 0u;
        g_stR[t]  = snr;
        if (level==3)
            g_thresh[t] = keyToFloat(g_bkA[t] + pv);  // exact fp32 order statistic
    }
    __syncthreads();
    for (int j=tid; j<LBINS; j+=1024) g_lvlhist[t][j]=0;   // prep next level
}

// ---------------- K6: quantize-dequantize, mask split by exact thresholds ----------------
__global__ void __launch_bounds__(256) k_quant(
        const float* __restrict__ x,
        const float* __restrict__ sl_, const float* __restrict__ zl_,
        const float* __restrict__ sh_, const float* __restrict__ zh_,
        float* __restrict__ out, int cols){
    int row = blockIdx.y;
    int col = (blockIdx.x*blockDim.x + threadIdx.x)*4;
    if (col >= cols) return;
    float lo = g_thresh[0];
    float hi = g_thresh[1];
    float sl = __ldg(&sl_[row]), zl = __ldg(&zl_[row]);
    float sh = __ldg(&sh_[row]), zh = __ldg(&zh_[row]);
    size_t base = (size_t)row*(size_t)cols + (size_t)col;
    float4 v = *reinterpret_cast<const float4*>(x + base);
    float in[4] = {v.x, v.y, v.z, v.w};
    float o[4];
    #pragma unroll
    for (int e=0;e<4;e++){
        float xv = in[e];
        bool  m  = (xv > lo) && (xv < hi);    // True = low-magnitude bulk (1-bit path)
        float s  = m ? sl : sh;
        float z  = m ? zl : zh;
        float mq = m ? 1.0f : 255.0f;
        float q  = __fadd_rn(rintf(__fdiv_rn(xv, s)), z);  // IEEE div + round-half-even = jnp
        q = fminf(fmaxf(q, 0.0f), mq);
        o[e] = __fmul_rn(s, __fadd_rn(q, -z));
    }
    *reinterpret_cast<float4*>(out + base) = make_float4(o[0], o[1], o[2], o[3]);
}

// ---------------- launch ----------------
extern "C" void kernel_launch(void* const* d_in, const int* in_sizes, int n_in,
                              void* d_out, int out_size){
    const float* x  = (const float*)d_in[0];
    const float* sl = (const float*)d_in[1];
    const float* zl = (const float*)d_in[2];
    const float* sh = (const float*)d_in[3];
    const float* zh = (const float*)d_in[4];
    float* out = (float*)d_out;

    long long n    = (long long)in_sizes[0];
    int rows       = in_sizes[1];
    int cols       = (int)(n / rows);
    long long high_num = (long long)((double)n * 0.1);   // replicates python int(n*0.1)
    long long khalf    = high_num / 2;
    unsigned pLo = (unsigned)(khalf - 1);                // 0-indexed sorted positions
    unsigned pHi = (unsigned)(n - khalf - 1);

    const int S = 262144;                                // sample count (stride = 172 here)
    int stride = (int)(n / S); if (stride < 1) stride = 1;
    unsigned tsLo = (unsigned)(pLo / (unsigned)stride);  // expected sample ranks
    unsigned tsHi = (unsigned)(pHi / (unsigned)stride);
    unsigned M = 2000;                                   // ~18-sigma bracket margin
    int n4 = (int)(n/4);

    k_zero<<<32,256>>>();
    k_sample<<<S/256,256>>>(x, n, stride);
    k_bracket<<<1,1024>>>(tsLo, tsHi, M);
    k_collect<<<1184,256>>>((const float4*)x, n4);
    for (int lvl=1; lvl<=3; lvl++){
        k_lvl<<<dim3(16,2),256>>>();
        k_scan<<<2,1024>>>(lvl, pLo, pHi);
    }
    dim3 gq((cols/4 + 255)/256, rows);
    k_quant<<<gq,256>>>(x, sl, zl, sh, zh, out, cols);
}

// round 11
// speedup vs baseline: 2.8129x; 2.8129x over previous
#include <cuda_runtime.h>
#include <stdint.h>

// ---------------- static device scratch (no allocations allowed) ----------------
#define SBINS 65536
#define LBINS 4096
#define BUFCAP (4u<<20)
#define STAGE_CAP 4096u

__device__ unsigned g_shist[SBINS];
__device__ unsigned g_lvlhist[2][LBINS];
__device__ unsigned g_bufCount[2];
__device__ unsigned g_cntBelow[2];
__device__ unsigned g_bkA[2];
__device__ unsigned g_bkB[2];
__device__ unsigned g_stS[2], g_stPM[2], g_stPV[2], g_stR[2];
__device__ float    g_thresh[2];
__device__ unsigned g_buf[2][BUFCAP];

// monotonic uint32 key: preserves float total order
__device__ __forceinline__ unsigned fkey(float f){
    unsigned b = __float_as_uint(f);
    return b ^ ((unsigned)(((int)b) >> 31) | 0x80000000u);
}
__device__ __forceinline__ float keyToFloat(unsigned k){
    unsigned b = (k & 0x80000000u) ? (k ^ 0x80000000u) : ~k;
    return __uint_as_float(b);
}

// ---------------- K0: zero scratch ----------------
__global__ void __launch_bounds__(256) k_zero(){
    int i  = blockIdx.x*blockDim.x + threadIdx.x;
    int st = gridDim.x*blockDim.x;
    for (int j=i; j<SBINS; j+=st) g_shist[j]=0;
    for (int j=i; j<2*LBINS; j+=st) (&g_lvlhist[0][0])[j]=0;
    if (i<2){ g_bufCount[i]=0; g_cntBelow[i]=0; }
}

// ---------------- K1: strided sample -> 16-bit-key histogram ----------------
__global__ void __launch_bounds__(256) k_sample(const float* __restrict__ x, long long n, int stride){
    long long s = (long long)(blockIdx.x*blockDim.x + threadIdx.x);
    long long i = s * (long long)stride;
    if (i < n){
        unsigned k = fkey(x[i]);
        atomicAdd(&g_shist[k>>16], 1u);
    }
}

// ---------------- K2: bracket both target ranks from sample CDF ----------------
__global__ void __launch_bounds__(1024,1) k_bracket(unsigned tsLo, unsigned tsHi, unsigned M){
    __shared__ unsigned ps[1024];
    __shared__ int aBin[2]; __shared__ int bBin[2];
    int tid  = threadIdx.x;
    int base = tid*64;
    unsigned s = 0;
    for (int j=0;j<64;j++) s += g_shist[base+j];
    ps[tid]=s;
    if (tid<2){ aBin[tid]=0; bBin[tid]=SBINS; }
    __syncthreads();
    for (int off=1; off<1024; off<<=1){
        unsigned v = (tid>=off)? ps[tid-off] : 0u;
        __syncthreads();
        ps[tid] += v;
        __syncthreads();
    }
    unsigned segExcl = ps[tid]-s;
    unsigned TA[2]; TA[0] = (tsLo>M)? tsLo-M:0u; TA[1] = (tsHi>M)? tsHi-M:0u;
    unsigned TB[2]; TB[0] = tsLo+M; TB[1] = tsHi+M;
    for (int t=0;t<2;t++){
        // largest boundary i with cum(i) <= TA  ->  a = i<<16  (cum monotone -> prefix set)
        unsigned run = segExcl; int best = -1;
        for (int j=0;j<64;j++){
            if (run <= TA[t]) best = base+j;
            run += g_shist[base+j];
        }
        if (best>=0) atomicMax(&aBin[t], best);
        // smallest boundary i with cum(i) >= TB -> b = i<<16
        run = segExcl;
        for (int j=0;j<64;j++){
            if (run >= TB[t]) { atomicMin(&bBin[t], base+j); break; }
            run += g_shist[base+j];
        }
    }
    __syncthreads();
    if (tid<2){
        int t = tid;
        unsigned a  = ((unsigned)aBin[t]) << 16;
        unsigned bb = (bBin[t] >= SBINS) ? 0xFFFFFFFFu : (((unsigned)bBin[t]) << 16);
        if (bb <= a) bb = a + 0x10000u;
        g_bkA[t]=a; g_bkB[t]=bb;
        unsigned W  = bb - a;                     // >= 0x10000
        unsigned L  = 32u - __clz(W - 1u);        // bits needed for window offsets
        unsigned s1 = (L>12u)? L-12u : 0u;
        g_stS[t]=s1; g_stPM[t]=0u; g_stPV[t]=0u; g_stR[t]=0u;
    }
}

// ---------------- K3: full scan — MLP=4 loads, ALU-only common path, smem-staged collect ----------------
__global__ void __launch_bounds__(256) k_collect(const float4* __restrict__ x4, int n4){
    __shared__ unsigned stage[2][STAGE_CAP];
    __shared__ unsigned scnt[2];
    __shared__ unsigned sred[2];
    __shared__ unsigned sbase[2];
    int tid = threadIdx.x;
    if (tid < 2){ scnt[tid]=0; sred[tid]=0; }
    __syncthreads();
    unsigned a0=g_bkA[0], w0=g_bkB[0]-g_bkA[0];
    unsigned a1=g_bkA[1], w1=g_bkB[1]-g_bkA[1];
    unsigned c0=0, c1=0;
    int idx = blockIdx.x*blockDim.x + tid;
    int st  = gridDim.x*blockDim.x;
    const float INF = __int_as_float(0x7F800000);   // sentinel: key=0xFF800000, above everything
    int iters  = (n4 + st - 1) / st;
    int oiters = (iters + 3) / 4;
    for (int ot=0; ot<oiters; ot++){
        int i0 = idx + (ot*4+0)*st;
        int i1 = idx + (ot*4+1)*st;
        int i2 = idx + (ot*4+2)*st;
        int i3 = idx + (ot*4+3)*st;
        float4 v[4];                                 // 4 independent loads in flight (MLP=4)
        v[0] = (i0<n4) ? x4[i0] : make_float4(INF,INF,INF,INF);
        v[1] = (i1<n4) ? x4[i1] : make_float4(INF,INF,INF,INF);
        v[2] = (i2<n4) ? x4[i2] : make_float4(INF,INF,INF,INF);
        v[3] = (i3<n4) ? x4[i3] : make_float4(INF,INF,INF,INF);
        #pragma unroll
        for (int b=0;b<4;b++){
            float vv[4] = {v[b].x, v[b].y, v[b].z, v[b].w};
            #pragma unroll
            for (int e=0;e<4;e++){
                unsigned k = fkey(vv[e]);
                c0 += (unsigned)(k < a0);
                c1 += (unsigned)(k < a1);
                if (k - a0 < w0){                    // k in [a0,b0): rare (~1.7%)
                    unsigned p = atomicAdd(&scnt[0], 1u);
                    if (p < STAGE_CAP) stage[0][p] = k;
                    else { unsigned g = atomicAdd(&g_bufCount[0],1u); if (g<BUFCAP) g_buf[0][g]=k; }
                }
                if (k - a1 < w1){                    // k in [a1,b1): rare
                    unsigned p = atomicAdd(&scnt[1], 1u);
                    if (p < STAGE_CAP) stage[1][p] = k;
                    else { unsigned g = atomicAdd(&g_bufCount[1],1u); if (g<BUFCAP) g_buf[1][g]=k; }
                }
            }
        }
    }
    // below-counts: warp reduce -> smem -> one global atomic per block per counter
    #pragma unroll
    for (int o=16;o>0;o>>=1){
        c0 += __shfl_down_sync(0xFFFFFFFFu, c0, o);
        c1 += __shfl_down_sync(0xFFFFFFFFu, c1, o);
    }
    if ((tid & 31) == 0){
        atomicAdd(&sred[0], c0);
        atomicAdd(&sred[1], c1);
    }
    __syncthreads();
    if (tid < 2){
        atomicAdd(&g_cntBelow[tid], sred[tid]);
        unsigned m = min(scnt[tid], STAGE_CAP);
        sbase[tid] = atomicAdd(&g_bufCount[tid], m);   // one reservation per buffer per block
    }
    __syncthreads();
    #pragma unroll
    for (int t=0;t<2;t++){
        unsigned m   = min(scnt[t], STAGE_CAP);
        unsigned bse = sbase[t];
        for (unsigned j=tid; j<m; j+=256u){
            unsigned g = bse + j;
            if (g < BUFCAP) g_buf[t][g] = stage[t][j];  // coalesced flush
        }
    }
}

// ---------------- K4: one radix level over the window buffer (both thresholds) ----------------
__global__ void __launch_bounds__(256) k_lvl(){
    __shared__ unsigned h[LBINS];
    int t   = blockIdx.y;
    int tid = threadIdx.x;
    for (int j=tid; j<LBINS; j+=blockDim.x) h[j]=0;
    __syncthreads();
    unsigned nb = min(g_bufCount[t], (unsigned)BUFCAP);
    unsigned s  = g_stS[t], pm = g_stPM[t], pv = g_stPV[t], a = g_bkA[t];
    unsigned idx = blockIdx.x*blockDim.x + tid;
    unsigned st  = gridDim.x*blockDim.x;
    for (unsigned i=idx; i<nb; i+=st){
        unsigned v = g_buf[t][i] - a;
        if ((v & pm) == pv) atomicAdd(&h[(v>>s) & (LBINS-1)], 1u);
    }
    __syncthreads();
    for (int j=tid; j<LBINS; j+=blockDim.x)
        if (h[j]) atomicAdd(&g_lvlhist[t][j], h[j]);
}

// ---------------- K5: scan level histogram, narrow selection; level 3 emits threshold ----------------
__global__ void __launch_bounds__(1024,1) k_scan(int level, unsigned pLo, unsigned pHi){
    __shared__ unsigned ps[1024];
    __shared__ unsigned sd, snr;
    int t   = blockIdx.x;
    int tid = threadIdx.x;
    if (tid == 0){ sd = LBINS-1; snr = 0; }   // defensive init (covered by scan-loop syncs)
    unsigned c[4];
    int base = tid*4;
    unsigned s4=0;
    #pragma unroll
    for (int j=0;j<4;j++){ c[j]=g_lvlhist[t][base+j]; s4+=c[j]; }
    ps[tid]=s4; __syncthreads();
    for (int off=1; off<1024; off<<=1){
        unsigned v = (tid>=off)? ps[tid-off] : 0u;
        __syncthreads();
        ps[tid] += v;
        __syncthreads();
    }
    unsigned total = ps[1023];
    unsigned r;
    if (level==1){
        unsigned p = (t==0)? pLo : pHi;
        unsigned below = g_cntBelow[t];
        r = (p >= below) ? (p - below) : 0u;  // rank inside the window buffer, clamped
    } else r = g_stR[t];
    if (total > 0 && r >= total) r = total - 1u;   // never let r escape the histogram
    unsigned segExcl = ps[tid]-s4;
    if (segExcl <= r && r < ps[tid]){   // exactly one thread matches
        unsigned run = segExcl;
        #pragma unroll
        for (int j=0;j<4;j++){
            if (r < run + c[j]){ sd = (unsigned)(base+j); snr = r - run; break; }
            run += c[j];
        }
    }
    __syncthreads();
    if (tid==0){
        unsigned s  = g_stS[t];
        unsigned pv = g_stPV[t] | (sd << s);
        g_stPV[t] = pv;
        g_stPM[t] = g_stPM[t] | (0xFFFu << s);
        g_stS[t]  = (s>=12u)? s-12u : 0u;
        g_stR[t]  = snr;
        if (level==3)
            g_thresh[t] = keyToFloat(g_bkA[t] + pv);  // exact fp32 order statistic
    }
    __syncthreads();
    for (int j=tid; j<LBINS; j+=1024) g_lvlhist[t][j]=0;   // prep next level
}

// ---------------- K6: quantize-dequantize, mask split by exact thresholds ----------------
__global__ void __launch_bounds__(256) k_quant(
        const float* __restrict__ x,
        const float* __restrict__ sl_, const float* __restrict__ zl_,
        const float* __restrict__ sh_, const float* __restrict__ zh_,
        float* __restrict__ out, int cols){
    int row = blockIdx.y;
    int col = (blockIdx.x*blockDim.x + threadIdx.x)*4;
    if (col >= cols) return;
    float lo = g_thresh[0];
    float hi = g_thresh[1];
    float sl = __ldg(&sl_[row]), zl = __ldg(&zl_[row]);
    float sh = __ldg(&sh_[row]), zh = __ldg(&zh_[row]);
    size_t base = (size_t)row*(size_t)cols + (size_t)col;
    float4 v = *reinterpret_cast<const float4*>(x + base);
    float in[4] = {v.x, v.y, v.z, v.w};
    float o[4];
    #pragma unroll
    for (int e=0;e<4;e++){
        float xv = in[e];
        bool  m  = (xv > lo) && (xv < hi);    // True = low-magnitude bulk (1-bit path)
        float s  = m ? sl : sh;
        float z  = m ? zl : zh;
        float mq = m ? 1.0f : 255.0f;
        float q  = __fadd_rn(rintf(__fdiv_rn(xv, s)), z);  // IEEE div + round-half-even = jnp
        q = fminf(fmaxf(q, 0.0f), mq);
        o[e] = __fmul_rn(s, __fadd_rn(q, -z));
    }
    *reinterpret_cast<float4*>(out + base) = make_float4(o[0], o[1], o[2], o[3]);
}

// ---------------- launch ----------------
extern "C" void kernel_launch(void* const* d_in, const int* in_sizes, int n_in,
                              void* d_out, int out_size){
    const float* x  = (const float*)d_in[0];
    const float* sl = (const float*)d_in[1];
    const float* zl = (const float*)d_in[2];
    const float* sh = (const float*)d_in[3];
    const float* zh = (const float*)d_in[4];
    float* out = (float*)d_out;

    long long n    = (long long)in_sizes[0];
    int rows       = in_sizes[1];
    int cols       = (int)(n / rows);
    long long high_num = (long long)((double)n * 0.1);   // replicates python int(n*0.1)
    long long khalf    = high_num / 2;
    unsigned pLo = (unsigned)(khalf - 1);                // 0-indexed sorted positions
    unsigned pHi = (unsigned)(n - khalf - 1);

    const int S = 262144;                                // sample count (stride = 172 here)
    int stride = (int)(n / S); if (stride < 1) stride = 1;
    unsigned tsLo = (unsigned)(pLo / (unsigned)stride);  // expected sample ranks
    unsigned tsHi = (unsigned)(pHi / (unsigned)stride);
    unsigned M = 2000;                                   // ~18-sigma bracket margin
    int n4 = (int)(n/4);

    k_zero<<<32,256>>>();
    k_sample<<<S/256,256>>>(x, n, stride);
    k_bracket<<<1,1024>>>(tsLo, tsHi, M);
    k_collect<<<1036,256>>>((const float4*)x, n4);       // 7 blocks/SM (32KB smem), one wave
    for (int lvl=1; lvl<=3; lvl++){
        k_lvl<<<dim3(16,2),256>>>();
        k_scan<<<2,1024>>>(lvl, pLo, pHi);
    }
    dim3 gq((cols/4 + 255)/256, rows);
    k_quant<<<gq,256>>>(x, sl, zl, sh, zh, out, cols);
}

// round 12
// speedup vs baseline: 2.8878x; 1.0266x over previous
#include <cuda_runtime.h>
#include <stdint.h>

// ---------------- static device scratch (no allocations allowed) ----------------
#define SBINS 65536
#define LBINS 4096
#define BUFCAP (4u<<20)
#define STAGE_CAP 4096u

__device__ unsigned g_shist[SBINS];
__device__ unsigned g_lvlhist[2][LBINS];
__device__ unsigned g_bufCount[2];
__device__ unsigned g_cntBelow[2];
__device__ unsigned g_bkA[2];
__device__ unsigned g_bkB[2];
__device__ unsigned g_stS[2], g_stPM[2], g_stPV[2], g_stR[2];
__device__ float    g_thresh[2];
__device__ unsigned g_buf[2][BUFCAP];

// monotonic uint32 key: preserves float total order
__device__ __forceinline__ unsigned fkey(float f){
    unsigned b = __float_as_uint(f);
    return b ^ ((unsigned)(((int)b) >> 31) | 0x80000000u);
}
__device__ __forceinline__ float keyToFloat(unsigned k){
    unsigned b = (k & 0x80000000u) ? (k ^ 0x80000000u) : ~k;
    return __uint_as_float(b);
}

// ---------------- K0: zero scratch ----------------
__global__ void __launch_bounds__(256) k_zero(){
    int i  = blockIdx.x*blockDim.x + threadIdx.x;
    int st = gridDim.x*blockDim.x;
    for (int j=i; j<SBINS; j+=st) g_shist[j]=0;
    for (int j=i; j<2*LBINS; j+=st) (&g_lvlhist[0][0])[j]=0;
    if (i<2){ g_bufCount[i]=0; g_cntBelow[i]=0; }
}

// ---------------- K1: strided sample -> 16-bit-key histogram ----------------
__global__ void __launch_bounds__(256) k_sample(const float* __restrict__ x, long long n, int stride){
    long long s = (long long)(blockIdx.x*blockDim.x + threadIdx.x);
    long long i = s * (long long)stride;
    if (i < n){
        unsigned k = fkey(x[i]);
        atomicAdd(&g_shist[k>>16], 1u);
    }
}

// ---------------- K2: bracket both target ranks from sample CDF ----------------
__global__ void __launch_bounds__(1024,1) k_bracket(unsigned tsLo, unsigned tsHi, unsigned M){
    __shared__ unsigned ps[1024];
    __shared__ int aBin[2]; __shared__ int bBin[2];
    int tid  = threadIdx.x;
    int base = tid*64;
    unsigned s = 0;
    for (int j=0;j<64;j++) s += g_shist[base+j];
    ps[tid]=s;
    if (tid<2){ aBin[tid]=0; bBin[tid]=SBINS; }
    __syncthreads();
    for (int off=1; off<1024; off<<=1){
        unsigned v = (tid>=off)? ps[tid-off] : 0u;
        __syncthreads();
        ps[tid] += v;
        __syncthreads();
    }
    unsigned segExcl = ps[tid]-s;
    unsigned TA[2]; TA[0] = (tsLo>M)? tsLo-M:0u; TA[1] = (tsHi>M)? tsHi-M:0u;
    unsigned TB[2]; TB[0] = tsLo+M; TB[1] = tsHi+M;
    for (int t=0;t<2;t++){
        // largest boundary i with cum(i) <= TA  ->  a = i<<16  (cum monotone -> prefix set)
        unsigned run = segExcl; int best = -1;
        for (int j=0;j<64;j++){
            if (run <= TA[t]) best = base+j;
            run += g_shist[base+j];
        }
        if (best>=0) atomicMax(&aBin[t], best);
        // smallest boundary i with cum(i) >= TB -> b = i<<16
        run = segExcl;
        for (int j=0;j<64;j++){
            if (run >= TB[t]) { atomicMin(&bBin[t], base+j); break; }
            run += g_shist[base+j];
        }
    }
    __syncthreads();
    if (tid<2){
        int t = tid;
        unsigned a  = ((unsigned)aBin[t]) << 16;
        unsigned bb = (bBin[t] >= SBINS) ? 0xFFFFFFFFu : (((unsigned)bBin[t]) << 16);
        if (bb <= a) bb = a + 0x10000u;
        g_bkA[t]=a; g_bkB[t]=bb;
        unsigned W  = bb - a;                     // >= 0x10000
        unsigned L  = 32u - __clz(W - 1u);        // bits needed for window offsets
        unsigned s1 = (L>12u)? L-12u : 0u;
        g_stS[t]=s1; g_stPM[t]=0u; g_stPV[t]=0u; g_stR[t]=0u;
    }
}

// ---------------- K3: full scan — MLP=4 loads, ALU-only common path, smem-staged collect ----------------
__global__ void __launch_bounds__(256) k_collect(const float4* __restrict__ x4, int n4){
    __shared__ unsigned stage[2][STAGE_CAP];
    __shared__ unsigned scnt[2];
    __shared__ unsigned sred[2];
    __shared__ unsigned sbase[2];
    int tid = threadIdx.x;
    if (tid < 2){ scnt[tid]=0; sred[tid]=0; }
    __syncthreads();
    unsigned a0=g_bkA[0], w0=g_bkB[0]-g_bkA[0];
    unsigned a1=g_bkA[1], w1=g_bkB[1]-g_bkA[1];
    unsigned c0=0, c1=0;
    int idx = blockIdx.x*blockDim.x + tid;
    int st  = gridDim.x*blockDim.x;
    const float INF = __int_as_float(0x7F800000);   // sentinel: key=0xFF800000, above everything
    int iters  = (n4 + st - 1) / st;
    int oiters = (iters + 3) / 4;
    for (int ot=0; ot<oiters; ot++){
        int i0 = idx + (ot*4+0)*st;
        int i1 = idx + (ot*4+1)*st;
        int i2 = idx + (ot*4+2)*st;
        int i3 = idx + (ot*4+3)*st;
        float4 v[4];                                 // 4 independent loads in flight (MLP=4)
        v[0] = (i0<n4) ? x4[i0] : make_float4(INF,INF,INF,INF);
        v[1] = (i1<n4) ? x4[i1] : make_float4(INF,INF,INF,INF);
        v[2] = (i2<n4) ? x4[i2] : make_float4(INF,INF,INF,INF);
        v[3] = (i3<n4) ? x4[i3] : make_float4(INF,INF,INF,INF);
        #pragma unroll
        for (int b=0;b<4;b++){
            float vv[4] = {v[b].x, v[b].y, v[b].z, v[b].w};
            #pragma unroll
            for (int e=0;e<4;e++){
                unsigned k = fkey(vv[e]);
                c0 += (unsigned)(k < a0);
                c1 += (unsigned)(k < a1);
                if (k - a0 < w0){                    // k in [a0,b0): rare (~1.7%)
                    unsigned p = atomicAdd(&scnt[0], 1u);
                    if (p < STAGE_CAP) stage[0][p] = k;
                    else { unsigned g = atomicAdd(&g_bufCount[0],1u); if (g<BUFCAP) g_buf[0][g]=k; }
                }
                if (k - a1 < w1){                    // k in [a1,b1): rare
                    unsigned p = atomicAdd(&scnt[1], 1u);
                    if (p < STAGE_CAP) stage[1][p] = k;
                    else { unsigned g = atomicAdd(&g_bufCount[1],1u); if (g<BUFCAP) g_buf[1][g]=k; }
                }
            }
        }
    }
    // below-counts: warp reduce -> smem -> one global atomic per block per counter
    #pragma unroll
    for (int o=16;o>0;o>>=1){
        c0 += __shfl_down_sync(0xFFFFFFFFu, c0, o);
        c1 += __shfl_down_sync(0xFFFFFFFFu, c1, o);
    }
    if ((tid & 31) == 0){
        atomicAdd(&sred[0], c0);
        atomicAdd(&sred[1], c1);
    }
    __syncthreads();
    if (tid < 2){
        atomicAdd(&g_cntBelow[tid], sred[tid]);
        unsigned m = min(scnt[tid], STAGE_CAP);
        sbase[tid] = atomicAdd(&g_bufCount[tid], m);   // one reservation per buffer per block
    }
    __syncthreads();
    #pragma unroll
    for (int t=0;t<2;t++){
        unsigned m   = min(scnt[t], STAGE_CAP);
        unsigned bse = sbase[t];
        for (unsigned j=tid; j<m; j+=256u){
            unsigned g = bse + j;
            if (g < BUFCAP) g_buf[t][g] = stage[t][j];  // coalesced flush
        }
    }
}

// ---------------- K4: one radix level over the window buffer (both thresholds) ----------------
__global__ void __launch_bounds__(256) k_lvl(){
    __shared__ unsigned h[LBINS];
    int t   = blockIdx.y;
    int tid = threadIdx.x;
    for (int j=tid; j<LBINS; j+=blockDim.x) h[j]=0;
    __syncthreads();
    unsigned nb = min(g_bufCount[t], (unsigned)BUFCAP);
    unsigned s  = g_stS[t], pm = g_stPM[t], pv = g_stPV[t], a = g_bkA[t];
    unsigned idx = blockIdx.x*blockDim.x + tid;
    unsigned st  = gridDim.x*blockDim.x;
    for (unsigned i=idx; i<nb; i+=st){
        unsigned v = g_buf[t][i] - a;
        if ((v & pm) == pv) atomicAdd(&h[(v>>s) & (LBINS-1)], 1u);
    }
    __syncthreads();
    for (int j=tid; j<LBINS; j+=blockDim.x)
        if (h[j]) atomicAdd(&g_lvlhist[t][j], h[j]);
}

// ---------------- K5: scan level histogram, narrow selection; level 3 emits threshold ----------------
__global__ void __launch_bounds__(1024,1) k_scan(int level, unsigned pLo, unsigned pHi){
    __shared__ unsigned ps[1024];
    __shared__ unsigned sd, snr;
    int t   = blockIdx.x;
    int tid = threadIdx.x;
    if (tid == 0){ sd = LBINS-1; snr = 0; }   // defensive init (covered by scan-loop syncs)
    unsigned c[4];
    int base = tid*4;
    unsigned s4=0;
    #pragma unroll
    for (int j=0;j<4;j++){ c[j]=g_lvlhist[t][base+j]; s4+=c[j]; }
    ps[tid]=s4; __syncthreads();
    for (int off=1; off<1024; off<<=1){
        unsigned v = (tid>=off)? ps[tid-off] : 0u;
        __syncthreads();
        ps[tid] += v;
        __syncthreads();
    }
    unsigned total = ps[1023];
    unsigned r;
    if (level==1){
        unsigned p = (t==0)? pLo : pHi;
        unsigned below = g_cntBelow[t];
        r = (p >= below) ? (p - below) : 0u;  // rank inside the window buffer, clamped
    } else r = g_stR[t];
    if (total > 0 && r >= total) r = total - 1u;   // never let r escape the histogram
    unsigned segExcl = ps[tid]-s4;
    if (segExcl <= r && r < ps[tid]){   // exactly one thread matches
        unsigned run = segExcl;
        #pragma unroll
        for (int j=0;j<4;j++){
            if (r < run + c[j]){ sd = (unsigned)(base+j); snr = r - run; break; }
            run += c[j];
        }
    }
    __syncthreads();
    if (tid==0){
        unsigned s  = g_stS[t];
        unsigned pv = g_stPV[t] | (sd << s);
        g_stPV[t] = pv;
        g_stPM[t] = g_stPM[t] | (0xFFFu << s);
        g_stS[t]  = (s>=12u)? s-12u : 0u;
        g_stR[t]  = snr;
        if (level==3)
            g_thresh[t] = keyToFloat(g_bkA[t] + pv);  // exact fp32 order statistic
    }
    __syncthreads();
    for (int j=tid; j<LBINS; j+=1024) g_lvlhist[t][j]=0;   // prep next level
}

// ---------------- K6: quantize-dequantize, 2x float4 per thread, streaming stores ----------------
__global__ void __launch_bounds__(256) k_quant(
        const float4* __restrict__ x4,
        const float* __restrict__ sl_, const float* __restrict__ zl_,
        const float* __restrict__ sh_, const float* __restrict__ zh_,
        float4* __restrict__ out4, int n4r){     // n4r = float4s per row
    int row = blockIdx.y;
    int f0  = blockIdx.x*512 + threadIdx.x;      // this block covers 512 float4s of the row
    int f1  = f0 + 256;
    float lo = g_thresh[0];
    float hi = g_thresh[1];
    float sl = __ldg(&sl_[row]), zl = __ldg(&zl_[row]);
    float sh = __ldg(&sh_[row]), zh = __ldg(&zh_[row]);
    size_t rbase = (size_t)row*(size_t)n4r;

    bool p0 = (f0 < n4r), p1 = (f1 < n4r);
    float4 v0, v1;                                // two independent loads in flight
    if (p0) v0 = x4[rbase + f0];
    if (p1) v1 = x4[rbase + f1];

    float in0[4], in1[4], o0[4], o1[4];
    if (p0){ in0[0]=v0.x; in0[1]=v0.y; in0[2]=v0.z; in0[3]=v0.w; }
    if (p1){ in1[0]=v1.x; in1[1]=v1.y; in1[2]=v1.z; in1[3]=v1.w; }

    #pragma unroll
    for (int e=0;e<4;e++){
        {
            float xv = p0 ? in0[e] : 1.0f;
            bool  m  = (xv > lo) && (xv < hi);    // True = low-magnitude bulk (1-bit path)
            float s  = m ? sl : sh;
            float z  = m ? zl : zh;
            float mq = m ? 1.0f : 255.0f;
            float q  = __fadd_rn(rintf(__fdiv_rn(xv, s)), z);  // IEEE div + round-half-even = jnp
            q = fminf(fmaxf(q, 0.0f), mq);
            o0[e] = __fmul_rn(s, __fadd_rn(q, -z));
        }
        {
            float xv = p1 ? in1[e] : 1.0f;
            bool  m  = (xv > lo) && (xv < hi);
            float s  = m ? sl : sh;
            float z  = m ? zl : zh;
            float mq = m ? 1.0f : 255.0f;
            float q  = __fadd_rn(rintf(__fdiv_rn(xv, s)), z);
            q = fminf(fmaxf(q, 0.0f), mq);
            o1[e] = __fmul_rn(s, __fadd_rn(q, -z));
        }
    }
    if (p0) __stcs(&out4[rbase + f0], make_float4(o0[0],o0[1],o0[2],o0[3]));  // evict-first: out never re-read
    if (p1) __stcs(&out4[rbase + f1], make_float4(o1[0],o1[1],o1[2],o1[3]));
}

// ---------------- launch ----------------
extern "C" void kernel_launch(void* const* d_in, const int* in_sizes, int n_in,
                              void* d_out, int out_size){
    const float* x  = (const float*)d_in[0];
    const float* sl = (const float*)d_in[1];
    const float* zl = (const float*)d_in[2];
    const float* sh = (const float*)d_in[3];
    const float* zh = (const float*)d_in[4];
    float* out = (float*)d_out;

    long long n    = (long long)in_sizes[0];
    int rows       = in_sizes[1];
    int cols       = (int)(n / rows);
    long long high_num = (long long)((double)n * 0.1);   // replicates python int(n*0.1)
    long long khalf    = high_num / 2;
    unsigned pLo = (unsigned)(khalf - 1);                // 0-indexed sorted positions
    unsigned pHi = (unsigned)(n - khalf - 1);

    const int S = 262144;                                // sample count (stride = 172 here)
    int stride = (int)(n / S); if (stride < 1) stride = 1;
    unsigned tsLo = (unsigned)(pLo / (unsigned)stride);  // expected sample ranks
    unsigned tsHi = (unsigned)(pHi / (unsigned)stride);
    unsigned M = 2000;                                   // ~18-sigma bracket margin
    int n4 = (int)(n/4);
    int n4r = cols/4;                                    // float4s per row (cols % 4 == 0 here)

    k_zero<<<32,256>>>();
    k_sample<<<S/256,256>>>(x, n, stride);
    k_bracket<<<1,1024>>>(tsLo, tsHi, M);
    k_collect<<<1036,256>>>((const float4*)x, n4);       // one wave, smem-staged
    for (int lvl=1; lvl<=3; lvl++){
        k_lvl<<<dim3(16,2),256>>>();
        k_scan<<<2,1024>>>(lvl, pLo, pHi);
    }
    dim3 gq((n4r + 511)/512, rows);                      // 512 float4s per block (2 per thread)
    k_quant<<<gq,256>>>((const float4*)x, sl, zl, sh, zh, (float4*)out, n4r);
}

// round 15
// speedup vs baseline: 3.7486x; 1.2981x over previous
#include <cuda_runtime.h>
#include <stdint.h>

// ---------------- static device scratch (no allocations allowed) ----------------
#define SBINS 65536
#define LBINS 4096
#define BUFCAP (4u<<20)
#define STAGE_CAP 4096u

__device__ unsigned g_shist[SBINS];
__device__ unsigned g_lvlhist[2][LBINS];
__device__ unsigned g_bufCount[2];
__device__ unsigned g_cntBelow[2];
__device__ unsigned g_bkA[2];
__device__ unsigned g_bkB[2];
__device__ float    g_fA[2], g_fB[2];          // float-domain window bounds
__device__ unsigned g_stS[2], g_stPM[2], g_stPV[2], g_stR[2];
__device__ float    g_thresh[2];
__device__ unsigned g_buf[2][BUFCAP];

// monotonic uint32 key: preserves float total order
__device__ __forceinline__ unsigned fkey(float f){
    unsigned b = __float_as_uint(f);
    return b ^ ((unsigned)(((int)b) >> 31) | 0x80000000u);
}
__device__ __forceinline__ float keyToFloat(unsigned k){
    unsigned b = (k & 0x80000000u) ? (k ^ 0x80000000u) : ~k;
    return __uint_as_float(b);
}
// valid (non-NaN) key range is [key(-inf), key(+inf)] = [0x007FFFFF, 0xFF800000]
__device__ __forceinline__ unsigned clampKey(unsigned k){
    if (k < 0x007FFFFFu) k = 0x007FFFFFu;
    if (k > 0xFF800000u) k = 0xFF800000u;
    return k;
}

// ---------------- K0: zero scratch ----------------
__global__ void __launch_bounds__(256) k_zero(){
    int i  = blockIdx.x*blockDim.x + threadIdx.x;
    int st = gridDim.x*blockDim.x;
    for (int j=i; j<SBINS; j+=st) g_shist[j]=0;
    for (int j=i; j<2*LBINS; j+=st) (&g_lvlhist[0][0])[j]=0;
    if (i<2){ g_bufCount[i]=0; g_cntBelow[i]=0; }
}

// ---------------- K1: strided sample -> 16-bit-key histogram ----------------
__global__ void __launch_bounds__(256) k_sample(const float* __restrict__ x, long long n, int stride){
    long long s = (long long)(blockIdx.x*blockDim.x + threadIdx.x);
    long long i = s * (long long)stride;
    if (i < n){
        unsigned k = fkey(x[i]);
        atomicAdd(&g_shist[k>>16], 1u);
    }
}

// ---------------- K2: bracket both target ranks from sample CDF ----------------
__global__ void __launch_bounds__(1024,1) k_bracket(unsigned tsLo, unsigned tsHi, unsigned M){
    __shared__ unsigned ps[1024];
    __shared__ int aBin[2]; __shared__ int bBin[2];
    int tid  = threadIdx.x;
    int base = tid*64;
    unsigned s = 0;
    for (int j=0;j<64;j++) s += g_shist[base+j];
    ps[tid]=s;
    if (tid<2){ aBin[tid]=0; bBin[tid]=SBINS; }
    __syncthreads();
    for (int off=1; off<1024; off<<=1){
        unsigned v = (tid>=off)? ps[tid-off] : 0u;
        __syncthreads();
        ps[tid] += v;
        __syncthreads();
    }
    unsigned segExcl = ps[tid]-s;
    unsigned TA[2]; TA[0] = (tsLo>M)? tsLo-M:0u; TA[1] = (tsHi>M)? tsHi-M:0u;
    unsigned TB[2]; TB[0] = tsLo+M; TB[1] = tsHi+M;
    for (int t=0;t<2;t++){
        // largest boundary i with cum(i) <= TA  ->  a = i<<16  (cum monotone -> prefix set)
        unsigned run = segExcl; int best = -1;
        for (int j=0;j<64;j++){
            if (run <= TA[t]) best = base+j;
            run += g_shist[base+j];
        }
        if (best>=0) atomicMax(&aBin[t], best);
        // smallest boundary i with cum(i) >= TB -> b = i<<16
        run = segExcl;
        for (int j=0;j<64;j++){
            if (run >= TB[t]) { atomicMin(&bBin[t], base+j); break; }
            run += g_shist[base+j];
        }
    }
    __syncthreads();
    if (tid<2){
        int t = tid;
        unsigned a  = ((unsigned)aBin[t]) << 16;
        unsigned bb = (bBin[t] >= SBINS) ? 0xFFFFFFFFu : (((unsigned)bBin[t]) << 16);
        if (bb <= a) bb = a + 0x10000u;
        g_bkA[t]=a; g_bkB[t]=bb;
        // float-domain bounds for the collect pass; clamp endpoints into non-NaN key range
        g_fA[t] = keyToFloat(clampKey(a));     // x < fA  <=>  key(x) < a   (finite data)
        g_fB[t] = keyToFloat(clampKey(bb));    // x < fB  <=>  key(x) < bb
        unsigned W  = bb - a;                     // >= 0x10000
        unsigned L  = 32u - __clz(W - 1u);        // bits needed for window offsets
        unsigned s1 = (L>12u)? L-12u : 0u;
        g_stS[t]=s1; g_stPM[t]=0u; g_stPV[t]=0u; g_stR[t]=0u;
    }
}

// ---------------- K3: full scan — guard-free exact grid, float compares, smem-staged collect ----------------
__device__ __forceinline__ void collect_elem(float xv,
        float fa0, float fb0, float fa1, float fb1,
        unsigned& c0, unsigned& c1,
        unsigned* stage0, unsigned* stage1, unsigned* scnt){
    c0 += (unsigned)(xv < fa0);
    c1 += (unsigned)(xv < fa1);
    if (xv >= fa0 && xv < fb0){                  // rare (~1.7%)
        unsigned k = fkey(xv);
        unsigned p = atomicAdd(&scnt[0], 1u);
        if (p < STAGE_CAP) stage0[p] = k;
        else { unsigned g = atomicAdd(&g_bufCount[0],1u); if (g<BUFCAP) g_buf[0][g]=k; }
    }
    if (xv >= fa1 && xv < fb1){                  // rare
        unsigned k = fkey(xv);
        unsigned p = atomicAdd(&scnt[1], 1u);
        if (p < STAGE_CAP) stage1[p] = k;
        else { unsigned g = atomicAdd(&g_bufCount[1],1u); if (g<BUFCAP) g_buf[1][g]=k; }
    }
}

__global__ void __launch_bounds__(256) k_collect(const float4* __restrict__ x4, int n4){
    __shared__ unsigned stage[2][STAGE_CAP];
    __shared__ unsigned scnt[2];
    __shared__ unsigned sred[2];
    __shared__ unsigned sbase[2];
    int tid = threadIdx.x;
    if (tid < 2){ scnt[tid]=0; sred[tid]=0; }
    __syncthreads();
    float fa0 = g_fA[0], fb0 = g_fB[0];
    float fa1 = g_fA[1], fb1 = g_fB[1];
    unsigned c0=0, c1=0;
    int idx = blockIdx.x*blockDim.x + tid;
    int st  = gridDim.x*blockDim.x;
    int iters = n4 / st;                          // grid sized so every thread runs full iters
    int i = idx;
    int ot = 0;
    for (; ot + 4 <= iters; ot += 4){             // MLP=4, no bounds checks, no sentinels
        float4 v0 = x4[i];
        float4 v1 = x4[i+st];
        float4 v2 = x4[i+2*st];
        float4 v3 = x4[i+3*st];
        i += 4*st;
        float4 vb[4] = {v0,v1,v2,v3};
        #pragma unroll
        for (int b=0;b<4;b++){
            collect_elem(vb[b].x, fa0,fb0,fa1,fb1, c0,c1, stage[0],stage[1],scnt);
            collect_elem(vb[b].y, fa0,fb0,fa1,fb1, c0,c1, stage[0],stage[1],scnt);
            collect_elem(vb[b].z, fa0,fb0,fa1,fb1, c0,c1, stage[0],stage[1],scnt);
            collect_elem(vb[b].w, fa0,fb0,fa1,fb1, c0,c1, stage[0],stage[1],scnt);
        }
    }
    for (; ot < iters; ot++){
        float4 v = x4[i]; i += st;
        collect_elem(v.x, fa0,fb0,fa1,fb1, c0,c1, stage[0],stage[1],scnt);
        collect_elem(v.y, fa0,fb0,fa1,fb1, c0,c1, stage[0],stage[1],scnt);
        collect_elem(v.z, fa0,fb0,fa1,fb1, c0,c1, stage[0],stage[1],scnt);
        collect_elem(v.w, fa0,fb0,fa1,fb1, c0,c1, stage[0],stage[1],scnt);
    }
    {   // tail elements (none when st divides n4, but stay generic)
        int t0 = iters*st + idx;
        if (t0 < n4){
            float4 v = x4[t0];
            collect_elem(v.x, fa0,fb0,fa1,fb1, c0,c1, stage[0],stage[1],scnt);
            collect_elem(v.y, fa0,fb0,fa1,fb1, c0,c1, stage[0],stage[1],scnt);
            collect_elem(v.z, fa0,fb0,fa1,fb1, c0,c1, stage[0],stage[1],scnt);
            collect_elem(v.w, fa0,fb0,fa1,fb1, c0,c1, stage[0],stage[1],scnt);
        }
    }
    // below-counts: warp reduce -> smem -> one global atomic per block per counter
    #pragma unroll
    for (int o=16;o>0;o>>=1){
        c0 += __shfl_down_sync(0xFFFFFFFFu, c0, o);
        c1 += __shfl_down_sync(0xFFFFFFFFu, c1, o);
    }
    if ((tid & 31) == 0){
        atomicAdd(&sred[0], c0);
        atomicAdd(&sred[1], c1);
    }
    __syncthreads();
    if (tid < 2){
        atomicAdd(&g_cntBelow[tid], sred[tid]);
        unsigned m = min(scnt[tid], STAGE_CAP);
        sbase[tid] = atomicAdd(&g_bufCount[tid], m);   // one reservation per buffer per block
    }
    __syncthreads();
    #pragma unroll
    for (int t=0;t<2;t++){
        unsigned m   = min(scnt[t], STAGE_CAP);
        unsigned bse = sbase[t];
        for (unsigned j=tid; j<m; j+=256u){
            unsigned g = bse + j;
            if (g < BUFCAP) g_buf[t][g] = stage[t][j];  // coalesced flush
        }
    }
}

// ---------------- K4: one radix level over the window buffer (both thresholds) ----------------
__global__ void __launch_bounds__(256) k_lvl(){
    __shared__ unsigned h[LBINS];
    int t   = blockIdx.y;
    int tid = threadIdx.x;
    for (int j=tid; j<LBINS; j+=blockDim.x) h[j]=0;
    __syncthreads();
    unsigned nb = min(g_bufCount[t], (unsigned)BUFCAP);
    unsigned s  = g_stS[t], pm = g_stPM[t], pv = g_stPV[t], a = g_bkA[t];
    unsigned idx = blockIdx.x*blockDim.x + tid;
    unsigned st  = gridDim.x*blockDim.x;
    for (unsigned i=idx; i<nb; i+=st){
        unsigned v = g_buf[t][i] - a;
        if ((v & pm) == pv) atomicAdd(&h[(v>>s) & (LBINS-1)], 1u);
    }
    __syncthreads();
    for (int j=tid; j<LBINS; j+=blockDim.x)
        if (h[j]) atomicAdd(&g_lvlhist[t][j], h[j]);
}

// ---------------- K5: scan level histogram, narrow selection; level 3 emits threshold ----------------
__global__ void __launch_bounds__(1024,1) k_scan(int level, unsigned pLo, unsigned pHi){
    __shared__ unsigned ps[1024];
    __shared__ unsigned sd, snr;
    int t   = blockIdx.x;
    int tid = threadIdx.x;
    if (tid == 0){ sd = LBINS-1; snr = 0; }   // defensive init (covered by scan-loop syncs)
    unsigned c[4];
    int base = tid*4;
    unsigned s4=0;
    #pragma unroll
    for (int j=0;j<4;j++){ c[j]=g_lvlhist[t][base+j]; s4+=c[j]; }
    ps[tid]=s4; __syncthreads();
    for (int off=1; off<1024; off<<=1){
        unsigned v = (tid>=off)? ps[tid-off] : 0u;
        __syncthreads();
        ps[tid] += v;
        __syncthreads();
    }
    unsigned total = ps[1023];
    unsigned r;
    if (level==1){
        unsigned p = (t==0)? pLo : pHi;
        unsigned below = g_cntBelow[t];
        r = (p >= below) ? (p - below) : 0u;  // rank inside the window buffer, clamped
    } else r = g_stR[t];
    if (total > 0 && r >= total) r = total - 1u;   // never let r escape the histogram
    unsigned segExcl = ps[tid]-s4;
    if (segExcl <= r && r < ps[tid]){   // exactly one thread matches
        unsigned run = segExcl;
        #pragma unroll
        for (int j=0;j<4;j++){
            if (r < run + c[j]){ sd = (unsigned)(base+j); snr = r - run; break; }
            run += c[j];
        }
    }
    __syncthreads();
    if (tid==0){
        unsigned s  = g_stS[t];
        unsigned pv = g_stPV[t] | (sd << s);
        g_stPV[t] = pv;
        g_stPM[t] = g_stPM[t] | (0xFFFu << s);
        g_stS[t]  = (s>=12u)? s-12u : 0u;
        g_stR[t]  = snr;
        if (level==3)
            g_thresh[t] = keyToFloat(g_bkA[t] + pv);  // exact fp32 order statistic
    }
    __syncthreads();
    for (int j=tid; j<LBINS; j+=1024) g_lvlhist[t][j]=0;   // prep next level
}

// ---------------- K6: quantize-dequantize, reciprocal-mul + folded clamp (no per-elem divide) ----------------
__device__ __forceinline__ float qdq_elem(float xv, float lo, float hi,
        float sl, float rl, float cLoL, float cHiL,
        float sh, float rh, float cLoH, float cHiH){
    bool  m  = (xv > lo) && (xv < hi);     // True = low-magnitude bulk (1-bit path)
    float s  = m ? sl : sh;
    float r  = m ? rl : rh;
    float cL = m ? cLoL : cLoH;
    float cH = m ? cHiL : cHiH;
    // reference: s*(clip(round(x/s)+z,0,mq)-z) == s*clip(round(x/s), -z, mq-z)  (integer fold, exact)
    float t  = rintf(__fmul_rn(xv, r));    // round-half-even; r = RN(1/s)
    t = fminf(fmaxf(t, cL), cH);
    return __fmul_rn(s, t);
}

__global__ void __launch_bounds__(256) k_quant(
        const float4* __restrict__ x4,
        const float* __restrict__ sl_, const float* __restrict__ zl_,
        const float* __restrict__ sh_, const float* __restrict__ zh_,
        float4* __restrict__ out4, int n4r){     // n4r = float4s per row
    int row = blockIdx.y;
    int f0  = blockIdx.x*512 + threadIdx.x;      // this block covers 512 float4s of the row
    int f1  = f0 + 256;
    float lo = g_thresh[0];
    float hi = g_thresh[1];
    float sl = __ldg(&sl_[row]), zl = __ldg(&zl_[row]);
    float sh = __ldg(&sh_[row]), zh = __ldg(&zh_[row]);
    float rl = __frcp_rn(sl),    rh = __frcp_rn(sh);      // 2 recips amortized over 8 elems
    float cLoL = -zl, cHiL = 1.0f   - zl;                 // maxq_low  = 1
    float cLoH = -zh, cHiH = 255.0f - zh;                 // maxq_high = 255
    size_t rbase = (size_t)row*(size_t)n4r;

    bool p0 = (f0 < n4r), p1 = (f1 < n4r);
    float4 v0, v1;                                // two independent loads in flight
    if (p0) v0 = x4[rbase + f0];
    if (p1) v1 = x4[rbase + f1];

    if (p0){
        float4 o;
        o.x = qdq_elem(v0.x, lo,hi, sl,rl,cLoL,cHiL, sh,rh,cLoH,cHiH);
        o.y = qdq_elem(v0.y, lo,hi, sl,rl,cLoL,cHiL, sh,rh,cLoH,cHiH);
        o.z = qdq_elem(v0.z, lo,hi, sl,rl,cLoL,cHiL, sh,rh,cLoH,cHiH);
        o.w = qdq_elem(v0.w, lo,hi, sl,rl,cLoL,cHiL, sh,rh,cLoH,cHiH);
        __stcs(&out4[rbase + f0], o);             // evict-first: out never re-read
    }
    if (p1){
        float4 o;
        o.x = qdq_elem(v1.x, lo,hi, sl,rl,cLoL,cHiL, sh,rh,cLoH,cHiH);
        o.y = qdq_elem(v1.y, lo,hi, sl,rl,cLoL,cHiL, sh,rh,cLoH,cHiH);
        o.z = qdq_elem(v1.z, lo,hi, sl,rl,cLoL,cHiL, sh,rh,cLoH,cHiH);
        o.w = qdq_elem(v1.w, lo,hi, sl,rl,cLoL,cHiL, sh,rh,cLoH,cHiH);
        __stcs(&out4[rbase + f1], o);
    }
}

// ---------------- launch ----------------
extern "C" void kernel_launch(void* const* d_in, const int* in_sizes, int n_in,
                              void* d_out, int out_size){
    const float* x  = (const float*)d_in[0];
    const float* sl = (const float*)d_in[1];
    const float* zl = (const float*)d_in[2];
    const float* sh = (const float*)d_in[3];
    const float* zh = (const float*)d_in[4];
    float* out = (float*)d_out;

    long long n    = (long long)in_sizes[0];
    int rows       = in_sizes[1];
    int cols       = (int)(n / rows);
    long long high_num = (long long)((double)n * 0.1);   // replicates python int(n*0.1)
    long long khalf    = high_num / 2;
    unsigned pLo = (unsigned)(khalf - 1);                // 0-indexed sorted positions
    unsigned pHi = (unsigned)(n - khalf - 1);

    const int S = 262144;                                // sample count (stride = 172 here)
    int stride = (int)(n / S); if (stride < 1) stride = 1;
    unsigned tsLo = (unsigned)(pLo / (unsigned)stride);  // expected sample ranks
    unsigned tsHi = (unsigned)(pHi / (unsigned)stride);
    unsigned M = 2000;                                   // ~18-sigma bracket margin
    int n4 = (int)(n/4);
    int n4r = cols/4;                                    // float4s per row (cols % 4 == 0 here)

    k_zero<<<32,256>>>();
    k_sample<<<S/256,256>>>(x, n, stride);
    k_bracket<<<1,1024>>>(tsLo, tsHi, M);
    k_collect<<<1024,256>>>((const float4*)x, n4);       // 262144 threads divides n4: guard-free
    for (int lvl=1; lvl<=3; lvl++){
        k_lvl<<<dim3(96,2),256>>>();                     // was (16,2): filter passes were starved
        k_scan<<<2,1024>>>(lvl, pLo, pHi);
    }
    dim3 gq((n4r + 511)/512, rows);                      // 512 float4s per block (2 per thread)
    k_quant<<<gq,256>>>((const float4*)x, sl, zl, sh, zh, (float4*)out, n4r);
}

// round 17
// speedup vs baseline: 3.9487x; 1.0534x over previous
#include <cuda_runtime.h>
#include <stdint.h>

// ---------------- static device scratch (no allocations allowed) ----------------
#define SBINS 65536
#define LBINS 4096
#define BUFCAP (4u<<20)
#define STAGE_CAP 3072u     // 2*3072*4 = 24.6KB smem -> 8 blocks/SM -> grid 1024 fits in ONE wave

__device__ unsigned g_shist[SBINS];
__device__ unsigned g_lvlhist[2][LBINS];
__device__ unsigned g_bufCount[2];
__device__ unsigned g_cntBelow[2];
__device__ unsigned g_bkA[2];
__device__ unsigned g_bkB[2];
__device__ float    g_fA[2], g_fB[2];          // float-domain window bounds
__device__ unsigned g_stS[2], g_stPM[2], g_stPV[2], g_stR[2];
__device__ float    g_thresh[2];
__device__ unsigned g_buf[2][BUFCAP];

// monotonic uint32 key: preserves float total order
__device__ __forceinline__ unsigned fkey(float f){
    unsigned b = __float_as_uint(f);
    return b ^ ((unsigned)(((int)b) >> 31) | 0x80000000u);
}
__device__ __forceinline__ float keyToFloat(unsigned k){
    unsigned b = (k & 0x80000000u) ? (k ^ 0x80000000u) : ~k;
    return __uint_as_float(b);
}
// valid (non-NaN) key range is [key(-inf), key(+inf)] = [0x007FFFFF, 0xFF800000]
__device__ __forceinline__ unsigned clampKey(unsigned k){
    if (k < 0x007FFFFFu) k = 0x007FFFFFu;
    if (k > 0xFF800000u) k = 0xFF800000u;
    return k;
}

// ---------------- K0: zero scratch ----------------
__global__ void __launch_bounds__(256) k_zero(){
    int i  = blockIdx.x*blockDim.x + threadIdx.x;
    int st = gridDim.x*blockDim.x;
    for (int j=i; j<SBINS; j+=st) g_shist[j]=0;
    for (int j=i; j<2*LBINS; j+=st) (&g_lvlhist[0][0])[j]=0;
    if (i<2){ g_bufCount[i]=0; g_cntBelow[i]=0; }
}

// ---------------- K1: strided sample -> 16-bit-key histogram ----------------
__global__ void __launch_bounds__(256) k_sample(const float* __restrict__ x, long long n, int stride){
    long long s = (long long)(blockIdx.x*blockDim.x + threadIdx.x);
    long long i = s * (long long)stride;
    if (i < n){
        unsigned k = fkey(x[i]);
        atomicAdd(&g_shist[k>>16], 1u);
    }
}

// ---------------- K2: bracket both target ranks from sample CDF ----------------
__global__ void __launch_bounds__(1024,1) k_bracket(unsigned tsLo, unsigned tsHi, unsigned M){
    __shared__ unsigned ps[1024];
    __shared__ int aBin[2]; __shared__ int bBin[2];
    int tid  = threadIdx.x;
    int base = tid*64;
    unsigned s = 0;
    for (int j=0;j<64;j++) s += g_shist[base+j];
    ps[tid]=s;
    if (tid<2){ aBin[tid]=0; bBin[tid]=SBINS; }
    __syncthreads();
    for (int off=1; off<1024; off<<=1){
        unsigned v = (tid>=off)? ps[tid-off] : 0u;
        __syncthreads();
        ps[tid] += v;
        __syncthreads();
    }
    unsigned segExcl = ps[tid]-s;
    unsigned TA[2]; TA[0] = (tsLo>M)? tsLo-M:0u; TA[1] = (tsHi>M)? tsHi-M:0u;
    unsigned TB[2]; TB[0] = tsLo+M; TB[1] = tsHi+M;
    for (int t=0;t<2;t++){
        // largest boundary i with cum(i) <= TA  ->  a = i<<16  (cum monotone -> prefix set)
        unsigned run = segExcl; int best = -1;
        for (int j=0;j<64;j++){
            if (run <= TA[t]) best = base+j;
            run += g_shist[base+j];
        }
        if (best>=0) atomicMax(&aBin[t], best);
        // smallest boundary i with cum(i) >= TB -> b = i<<16
        run = segExcl;
        for (int j=0;j<64;j++){
            if (run >= TB[t]) { atomicMin(&bBin[t], base+j); break; }
            run += g_shist[base+j];
        }
    }
    __syncthreads();
    if (tid<2){
        int t = tid;
        unsigned a  = ((unsigned)aBin[t]) << 16;
        unsigned bb = (bBin[t] >= SBINS) ? 0xFFFFFFFFu : (((unsigned)bBin[t]) << 16);
        if (bb <= a) bb = a + 0x10000u;
        g_bkA[t]=a; g_bkB[t]=bb;
        // float-domain bounds for the collect pass; clamp endpoints into non-NaN key range
        g_fA[t] = keyToFloat(clampKey(a));     // x < fA  <=>  key(x) < a   (finite data)
        g_fB[t] = keyToFloat(clampKey(bb));    // x < fB  <=>  key(x) < bb
        unsigned W  = bb - a;                     // >= 0x10000
        unsigned L  = 32u - __clz(W - 1u);        // bits needed for window offsets (16..~20 here)
        unsigned s1 = (L>12u)? L-12u : 0u;
        g_stS[t]=s1; g_stPM[t]=0u; g_stPV[t]=0u; g_stR[t]=0u;
    }
}

// ---------------- K3: full scan — guard-free exact grid, float compares, smem-staged collect ----------------
__device__ __forceinline__ void collect_elem(float xv,
        float fa0, float fb0, float fa1, float fb1,
        unsigned& c0, unsigned& c1,
        unsigned* stage0, unsigned* stage1, unsigned* scnt){
    c0 += (unsigned)(xv < fa0);
    c1 += (unsigned)(xv < fa1);
    if (xv >= fa0 && xv < fb0){                  // rare (~1.7%)
        unsigned k = fkey(xv);
        unsigned p = atomicAdd(&scnt[0], 1u);
        if (p < STAGE_CAP) stage0[p] = k;
        else { unsigned g = atomicAdd(&g_bufCount[0],1u); if (g<BUFCAP) g_buf[0][g]=k; }
    }
    if (xv >= fa1 && xv < fb1){                  // rare
        unsigned k = fkey(xv);
        unsigned p = atomicAdd(&scnt[1], 1u);
        if (p < STAGE_CAP) stage1[p] = k;
        else { unsigned g = atomicAdd(&g_bufCount[1],1u); if (g<BUFCAP) g_buf[1][g]=k; }
    }
}

__global__ void __launch_bounds__(256) k_collect(const float4* __restrict__ x4, int n4){
    __shared__ unsigned stage[2][STAGE_CAP];
    __shared__ unsigned scnt[2];
    __shared__ unsigned sred[2];
    __shared__ unsigned sbase[2];
    int tid = threadIdx.x;
    if (tid < 2){ scnt[tid]=0; sred[tid]=0; }
    __syncthreads();
    float fa0 = g_fA[0], fb0 = g_fB[0];
    float fa1 = g_fA[1], fb1 = g_fB[1];
    unsigned c0=0, c1=0;
    int idx = blockIdx.x*blockDim.x + tid;
    int st  = gridDim.x*blockDim.x;
    int iters = n4 / st;                          // grid sized so every thread runs full iters
    int i = idx;
    int ot = 0;
    for (; ot + 4 <= iters; ot += 4){             // MLP=4, no bounds checks, no sentinels
        float4 v0 = x4[i];
        float4 v1 = x4[i+st];
        float4 v2 = x4[i+2*st];
        float4 v3 = x4[i+3*st];
        i += 4*st;
        float4 vb[4] = {v0,v1,v2,v3};
        #pragma unroll
        for (int b=0;b<4;b++){
            collect_elem(vb[b].x, fa0,fb0,fa1,fb1, c0,c1, stage[0],stage[1],scnt);
            collect_elem(vb[b].y, fa0,fb0,fa1,fb1, c0,c1, stage[0],stage[1],scnt);
            collect_elem(vb[b].z, fa0,fb0,fa1,fb1, c0,c1, stage[0],stage[1],scnt);
            collect_elem(vb[b].w, fa0,fb0,fa1,fb1, c0,c1, stage[0],stage[1],scnt);
        }
    }
    for (; ot < iters; ot++){
        float4 v = x4[i]; i += st;
        collect_elem(v.x, fa0,fb0,fa1,fb1, c0,c1, stage[0],stage[1],scnt);
        collect_elem(v.y, fa0,fb0,fa1,fb1, c0,c1, stage[0],stage[1],scnt);
        collect_elem(v.z, fa0,fb0,fa1,fb1, c0,c1, stage[0],stage[1],scnt);
        collect_elem(v.w, fa0,fb0,fa1,fb1, c0,c1, stage[0],stage[1],scnt);
    }
    {   // tail elements (none when st divides n4, but stay generic)
        int t0 = iters*st + idx;
        if (t0 < n4){
            float4 v = x4[t0];
            collect_elem(v.x, fa0,fb0,fa1,fb1, c0,c1, stage[0],stage[1],scnt);
            collect_elem(v.y, fa0,fb0,fa1,fb1, c0,c1, stage[0],stage[1],scnt);
            collect_elem(v.z, fa0,fb0,fa1,fb1, c0,c1, stage[0],stage[1],scnt);
            collect_elem(v.w, fa0,fb0,fa1,fb1, c0,c1, stage[0],stage[1],scnt);
        }
    }
    // below-counts: warp reduce -> smem -> one global atomic per block per counter
    #pragma unroll
    for (int o=16;o>0;o>>=1){
        c0 += __shfl_down_sync(0xFFFFFFFFu, c0, o);
        c1 += __shfl_down_sync(0xFFFFFFFFu, c1, o);
    }
    if ((tid & 31) == 0){
        atomicAdd(&sred[0], c0);
        atomicAdd(&sred[1], c1);
    }
    __syncthreads();
    if (tid < 2){
        atomicAdd(&g_cntBelow[tid], sred[tid]);
        unsigned m = min(scnt[tid], STAGE_CAP);
        sbase[tid] = atomicAdd(&g_bufCount[tid], m);   // one reservation per buffer per block
    }
    __syncthreads();
    #pragma unroll
    for (int t=0;t<2;t++){
        unsigned m   = min(scnt[t], STAGE_CAP);
        unsigned bse = sbase[t];
        for (unsigned j=tid; j<m; j+=256u){
            unsigned g = bse + j;
            if (g < BUFCAP) g_buf[t][g] = stage[t][j];  // coalesced flush
        }
    }
}

// ---------------- K4: one radix level over the window buffer (both thresholds) ----------------
__global__ void __launch_bounds__(256) k_lvl(){
    __shared__ unsigned h[LBINS];
    int t   = blockIdx.y;
    int tid = threadIdx.x;
    for (int j=tid; j<LBINS; j+=blockDim.x) h[j]=0;
    __syncthreads();
    unsigned nb = min(g_bufCount[t], (unsigned)BUFCAP);
    unsigned s  = g_stS[t], pm = g_stPM[t], pv = g_stPV[t], a = g_bkA[t];
    unsigned idx = blockIdx.x*blockDim.x + tid;
    unsigned st  = gridDim.x*blockDim.x;
    for (unsigned i=idx; i<nb; i+=st){
        unsigned v = g_buf[t][i] - a;
        if ((v & pm) == pv) atomicAdd(&h[(v>>s) & (LBINS-1)], 1u);
    }
    __syncthreads();
    for (int j=tid; j<LBINS; j+=blockDim.x)
        if (h[j]) atomicAdd(&g_lvlhist[t][j], h[j]);
}

// ---------------- K5: scan level histogram (shfl-scan), narrow; level 2 emits threshold ----------------
// Window width W has L in [16, ~20] bits here, so two 12-bit levels always pin the exact key:
// level-2 entry shift = max(L-24, 0) = 0  ->  after level 2 the full offset pv is resolved.
__global__ void __launch_bounds__(1024,1) k_scan(int level, unsigned pLo, unsigned pHi){
    __shared__ unsigned wsum[32];
    __shared__ unsigned sd, snr;
    int t    = blockIdx.x;
    int tid  = threadIdx.x;
    int lane = tid & 31, wid = tid >> 5;
    if (tid == 0){ sd = LBINS-1; snr = 0; }   // defensive init
    unsigned c[4];
    int base = tid*4;
    unsigned s4=0;
    #pragma unroll
    for (int j=0;j<4;j++){ c[j]=g_lvlhist[t][base+j]; s4+=c[j]; }
    // warp-level inclusive scan of s4
    unsigned inc = s4;
    #pragma unroll
    for (int o=1;o<32;o<<=1){
        unsigned v = __shfl_up_sync(0xFFFFFFFFu, inc, o);
        if (lane >= o) inc += v;
    }
    if (lane == 31) wsum[wid] = inc;
    __syncthreads();
    if (wid == 0){
        unsigned w = wsum[lane];
        #pragma unroll
        for (int o=1;o<32;o<<=1){
            unsigned v = __shfl_up_sync(0xFFFFFFFFu, w, o);
            if (lane >= o) w += v;
        }
        wsum[lane] = w;
    }
    __syncthreads();
    unsigned incl  = inc + (wid ? wsum[wid-1] : 0u);
    unsigned total = wsum[31];
    unsigned r;
    if (level==1){
        unsigned p = (t==0)? pLo : pHi;
        unsigned below = g_cntBelow[t];
        r = (p >= below) ? (p - below) : 0u;  // rank inside the window buffer, clamped
    } else r = g_stR[t];
    if (total > 0 && r >= total) r = total - 1u;   // never let r escape the histogram
    unsigned segExcl = incl - s4;
    if (segExcl <= r && r < incl){   // exactly one thread matches
        unsigned run = segExcl;
        #pragma unroll
        for (int j=0;j<4;j++){
            if (r < run + c[j]){ sd = (unsigned)(base+j); snr = r - run; break; }
            run += c[j];
        }
    }
    __syncthreads();
    if (tid==0){
        unsigned s  = g_stS[t];
        unsigned pv = g_stPV[t] | (sd << s);
        g_stPV[t] = pv;
        g_stPM[t] = g_stPM[t] | (0xFFFu << s);
        g_stS[t]  = (s>=12u)? s-12u : 0u;
        g_stR[t]  = snr;
        if (level==2)
            g_thresh[t] = keyToFloat(g_bkA[t] + pv);  // exact fp32 order statistic
    }
    __syncthreads();
    for (int j=tid; j<LBINS; j+=1024) g_lvlhist[t][j]=0;   // prep next level
}

// ---------------- K6: quantize-dequantize, 4 rows x 256 cols per block (MLP=4, broadcast scales) ----------------
__device__ __forceinline__ float qdq_elem(float xv, float lo, float hi,
        float sl, float rl, float cLoL, float cHiL,
        float sh, float rh, float cLoH, float cHiH){
    bool  m  = (xv > lo) && (xv < hi);     // True = low-magnitude bulk (1-bit path)
    float s  = m ? sl : sh;
    float r  = m ? rl : rh;
    float cL = m ? cLoL : cLoH;
    float cH = m ? cHiL : cHiH;
    // reference: s*(clip(round(x/s)+z,0,mq)-z) == s*clip(round(x/s), -z, mq-z)  (integer fold, exact)
    float t  = rintf(__fmul_rn(xv, r));    // round-half-even; r = RN(1/s)
    t = fminf(fmaxf(t, cL), cH);
    return __fmul_rn(s, t);
}

__global__ void __launch_bounds__(256) k_quant(
        const float4* __restrict__ x4,
        const float* __restrict__ sl_, const float* __restrict__ zl_,
        const float* __restrict__ sh_, const float* __restrict__ zh_,
        float4* __restrict__ out4, int n4r){     // n4r = float4s per row
    int col = blockIdx.x*256 + threadIdx.x;
    if (col >= n4r) return;
    int r0  = blockIdx.y*4;                      // this block covers rows r0..r0+3
    float lo = g_thresh[0];
    float hi = g_thresh[1];

    float sl[4], rl[4], cLoL[4], cHiL[4], sh[4], rh[4], cLoH[4], cHiH[4];
    #pragma unroll
    for (int j=0;j<4;j++){                       // block-uniform scale loads (L1 broadcast)
        float s0 = __ldg(&sl_[r0+j]), z0 = __ldg(&zl_[r0+j]);
        float s1 = __ldg(&sh_[r0+j]), z1 = __ldg(&zh_[r0+j]);
        sl[j]=s0; rl[j]=__frcp_rn(s0); cLoL[j]=-z0; cHiL[j]=1.0f  -z0;   // maxq_low  = 1
        sh[j]=s1; rh[j]=__frcp_rn(s1); cLoH[j]=-z1; cHiH[j]=255.0f-z1;   // maxq_high = 255
    }
    size_t p0 = (size_t)r0*(size_t)n4r + (size_t)col;
    float4 v[4];                                  // 4 independent loads in flight (4 rows)
    v[0] = x4[p0];
    v[1] = x4[p0 +   (size_t)n4r];
    v[2] = x4[p0 + 2*(size_t)n4r];
    v[3] = x4[p0 + 3*(size_t)n4r];
    #pragma unroll
    for (int j=0;j<4;j++){
        float4 o;
        o.x = qdq_elem(v[j].x, lo,hi, sl[j],rl[j],cLoL[j],cHiL[j], sh[j],rh[j],cLoH[j],cHiH[j]);
        o.y = qdq_elem(v[j].y, lo,hi, sl[j],rl[j],cLoL[j],cHiL[j], sh[j],rh[j],cLoH[j],cHiH[j]);
        o.z = qdq_elem(v[j].z, lo,hi, sl[j],rl[j],cLoL[j],cHiL[j], sh[j],rh[j],cLoH[j],cHiH[j]);
        o.w = qdq_elem(v[j].w, lo,hi, sl[j],rl[j],cLoL[j],cHiL[j], sh[j],rh[j],cLoH[j],cHiH[j]);
        __stcs(&out4[p0 + (size_t)j*(size_t)n4r], o);   // evict-first: out never re-read
    }
}

// ---------------- launch ----------------
extern "C" void kernel_launch(void* const* d_in, const int* in_sizes, int n_in,
                              void* d_out, int out_size){
    const float* x  = (const float*)d_in[0];
    const float* sl = (const float*)d_in[1];
    const float* zl = (const float*)d_in[2];
    const float* sh = (const float*)d_in[3];
    const float* zh = (const float*)d_in[4];
    float* out = (float*)d_out;

    long long n    = (long long)in_sizes[0];
    int rows       = in_sizes[1];
    int cols       = (int)(n / rows);
    long long high_num = (long long)((double)n * 0.1);   // replicates python int(n*0.1)
    long long khalf    = high_num / 2;
    unsigned pLo = (unsigned)(khalf - 1);                // 0-indexed sorted positions
    unsigned pHi = (unsigned)(n - khalf - 1);

    const int S = 262144;                                // sample count (stride = 172 here)
    int stride = (int)(n / S); if (stride < 1) stride = 1;
    unsigned tsLo = (unsigned)(pLo / (unsigned)stride);  // expected sample ranks
    unsigned tsHi = (unsigned)(pHi / (unsigned)stride);
    unsigned M = 2000;                                   // ~18-sigma bracket margin
    int n4 = (int)(n/4);
    int n4r = cols/4;                                    // float4s per row (cols % 4 == 0 here)

    k_zero<<<32,256>>>();
    k_sample<<<S/256,256>>>(x, n, stride);
    k_bracket<<<1,1024>>>(tsLo, tsHi, M);
    k_collect<<<1024,256>>>((const float4*)x, n4);       // guard-free, single wave now
    for (int lvl=1; lvl<=2; lvl++){                      // 2 levels resolve L<=24 bits exactly
        k_lvl<<<dim3(96,2),256>>>();
        k_scan<<<2,1024>>>(lvl, pLo, pHi);
    }
    dim3 gq((n4r + 255)/256, rows/4);                    // 4 rows x 256 float4-cols per block
    k_quant<<<gq,256>>>((const float4*)x, sl, zl, sh, zh, (float4*)out, n4r);
}